// round 3
// baseline (speedup 1.0000x reference)
#include <cuda_runtime.h>
#include <math_constants.h>

#define N_PTS 65536
#define KNNK 54
#define GRIDD 16
#define NCELL 4096
#define CELLH 0.0625f
#define NBLK 256

#define TWO_PI_F 6.28318530717958647692f
#define PI_F     3.14159265358979323846f
#define SQRT3_F  1.73205080756887729353f

// ---------------- scratch (static device memory; no allocation) ----------------
__device__ float4 d_sorted[N_PTS];
__device__ int d_cellStart[NCELL + 1];
__device__ int d_cellPtr[NCELL];
__device__ int d_cnt[NCELL];
__device__ int d_knn[N_PTS * KNNK];
__device__ float d_h[N_PTS * KNNK * 10];   // 141.6 MB
__device__ float d_part[NBLK * 20];
__device__ float d_bn[20];

__device__ __forceinline__ int cellCoord(float v) {
    int c = (int)floorf(v * 16.0f);
    c = c < 0 ? 0 : c;
    return c > (GRIDD - 1) ? (GRIDD - 1) : c;
}

// XLA-style sum of squares: ((x*x + y*y) + z*z), separate mul/add, round-to-nearest
__device__ __forceinline__ float sumsq_rn(float x, float y, float z) {
    return __fadd_rn(__fadd_rn(__fmul_rn(x, x), __fmul_rn(y, y)), __fmul_rn(z, z));
}

// cuBLAS-style K=3 dot: ascending-k fma chain with zero-init accumulator
__device__ __forceinline__ float dot3_fma(float ax, float ay, float az,
                                          float bx, float by, float bz) {
    return __fmaf_rn(az, bz, __fmaf_rn(ay, by, __fmul_rn(ax, bx)));
}

// ---------------- grid build ----------------
__global__ void zeroK() {
    int i = blockIdx.x * blockDim.x + threadIdx.x;
    if (i < NCELL) d_cnt[i] = 0;
}

__global__ void countK(const float* __restrict__ c) {
    int i = blockIdx.x * blockDim.x + threadIdx.x;
    if (i >= N_PTS) return;
    int cx = cellCoord(c[3 * i]);
    int cy = cellCoord(c[3 * i + 1]);
    int cz = cellCoord(c[3 * i + 2]);
    atomicAdd(&d_cnt[(cz * GRIDD + cy) * GRIDD + cx], 1);
}

__global__ __launch_bounds__(1024) void scanK() {
    __shared__ int s[1024];
    int t = threadIdx.x;
    int v0 = d_cnt[4 * t], v1 = d_cnt[4 * t + 1], v2 = d_cnt[4 * t + 2], v3 = d_cnt[4 * t + 3];
    int tot = v0 + v1 + v2 + v3;
    s[t] = tot;
    __syncthreads();
    for (int off = 1; off < 1024; off <<= 1) {
        int x = (t >= off) ? s[t - off] : 0;
        __syncthreads();
        s[t] += x;
        __syncthreads();
    }
    int excl = s[t] - tot;
    d_cellStart[4 * t] = excl;
    d_cellStart[4 * t + 1] = excl + v0;
    d_cellStart[4 * t + 2] = excl + v0 + v1;
    d_cellStart[4 * t + 3] = excl + v0 + v1 + v2;
    d_cellPtr[4 * t] = excl;
    d_cellPtr[4 * t + 1] = excl + v0;
    d_cellPtr[4 * t + 2] = excl + v0 + v1;
    d_cellPtr[4 * t + 3] = excl + v0 + v1 + v2;
    if (t == 1023) d_cellStart[NCELL] = s[1023];
}

__global__ void scatterK(const float* __restrict__ c) {
    int i = blockIdx.x * blockDim.x + threadIdx.x;
    if (i >= N_PTS) return;
    float x = c[3 * i], y = c[3 * i + 1], z = c[3 * i + 2];
    int cid = (cellCoord(z) * GRIDD + cellCoord(y)) * GRIDD + cellCoord(x);
    int pos = atomicAdd(&d_cellPtr[cid], 1);
    d_sorted[pos] = make_float4(x, y, z, __int_as_float(i));
}

// ---------------- KNN (grid-ordered queries, expanding rings) ----------------
__global__ __launch_bounds__(256) void knnK() {
    int t = blockIdx.x * blockDim.x + threadIdx.x;
    if (t >= N_PTS) return;
    float4 q = d_sorted[t];
    int qi = __float_as_int(q.w);
    float qx = q.x, qy = q.y, qz = q.z;
    float qsq = sumsq_rn(qx, qy, qz);                 // matches ref's sum(q*q)
    int cx = cellCoord(qx), cy = cellCoord(qy), cz = cellCoord(qz);

    float bd[KNNK];
    int bi[KNNK];
#pragma unroll
    for (int j = 0; j < KNNK; j++) { bd[j] = CUDART_INF_F; bi[j] = 0x7FFFFFFF; }

    int maxm = cx; if (GRIDD - 1 - cx > maxm) maxm = GRIDD - 1 - cx;
    if (cy > maxm) maxm = cy; if (GRIDD - 1 - cy > maxm) maxm = GRIDD - 1 - cy;
    if (cz > maxm) maxm = cz; if (GRIDD - 1 - cz > maxm) maxm = GRIDD - 1 - cz;

    float worst = CUDART_INF_F;
    int worsti = 0x7FFFFFFF;

    for (int m = 0;; m++) {
        int zlo = cz - m < 0 ? 0 : cz - m;
        int zhi = cz + m > GRIDD - 1 ? GRIDD - 1 : cz + m;
        for (int z = zlo; z <= zhi; z++) {
            int adz = z - cz; adz = adz < 0 ? -adz : adz;
            int ylo = cy - m < 0 ? 0 : cy - m;
            int yhi = cy + m > GRIDD - 1 ? GRIDD - 1 : cy + m;
            for (int y = ylo; y <= yhi; y++) {
                int ady = y - cy; ady = ady < 0 ? -ady : ady;
                int xlo = cx - m < 0 ? 0 : cx - m;
                int xhi = cx + m > GRIDD - 1 ? GRIDD - 1 : cx + m;
                for (int x = xlo; x <= xhi; x++) {
                    int adx = x - cx; adx = adx < 0 ? -adx : adx;
                    int cheb = adx > ady ? adx : ady;
                    if (adz > cheb) cheb = adz;
                    if (cheb != m) continue;
                    int cid = (z * GRIDD + y) * GRIDD + x;
                    int s = d_cellStart[cid], e = d_cellStart[cid + 1];
                    for (int p = s; p < e; p++) {
                        float4 pt = d_sorted[p];
                        // bit-match reference: d = (qsq + sq) - 2*dot, all round-to-nearest,
                        // dot as ascending-k fma chain (cuBLAS), sq as mul/add reduce (XLA)
                        float psq = sumsq_rn(pt.x, pt.y, pt.z);
                        float dot = dot3_fma(qx, qy, qz, pt.x, pt.y, pt.z);
                        float d = __fsub_rn(__fadd_rn(qsq, psq), __fmul_rn(2.0f, dot));
                        int pi = __float_as_int(pt.w);
                        if (d < worst || (d == worst && pi < worsti)) {
                            int j = KNNK - 1;
                            while (j > 0 && (bd[j - 1] > d || (bd[j - 1] == d && bi[j - 1] > pi))) {
                                bd[j] = bd[j - 1]; bi[j] = bi[j - 1]; j--;
                            }
                            bd[j] = d; bi[j] = pi;
                            worst = bd[KNNK - 1]; worsti = bi[KNNK - 1];
                        }
                    }
                }
            }
        }
        float rr = (float)m * CELLH;
        // safety margin: d carries ~5e-7 absolute cancellation noise; don't let a
        // marginal cutoff drop a point the all-pairs reference would have kept
        if (worst + 4e-6f < rr * rr) break;
        if (m >= maxm) break;         // whole grid covered
    }
    for (int j = 0; j < KNNK; j++) d_knn[qi * KNNK + j] = bi[j];
}

// ---------------- features + layer1 + BN partial sums ----------------
__global__ __launch_bounds__(256) void featK(const float* __restrict__ cen,
                                             const float* __restrict__ W1,
                                             const float* __restrict__ b1) {
    __shared__ float sW1[100], sb1[10];
    __shared__ float red[256];
    int tid = threadIdx.x;
    if (tid < 100) sW1[tid] = W1[tid];
    if (tid < 10) sb1[tid] = b1[tid];
    __syncthreads();

    int p = blockIdx.x * blockDim.x + tid;

    float gx[54], gy[54], gz[54], phiA[54];
    float skey[54];
    int perm[54];

    float qx = cen[3 * p], qy = cen[3 * p + 1], qz = cen[3 * p + 2];
    for (int j = 0; j < 54; j++) {
        int nb = d_knn[p * 54 + j];
        float x = __fsub_rn(cen[3 * nb], qx);
        float y = __fsub_rn(cen[3 * nb + 1], qy);
        float z = __fsub_rn(cen[3 * nb + 2], qz);
        gx[j] = x; gy[j] = y; gz[j] = z;
        // rotated = g @ ROT, ascending-k fma chains (matches XLA/cuBLAS dot)
        float rx = __fmaf_rn(z, -0.5f,    __fmaf_rn(y, 0.7071f, __fmul_rn(x,  0.5f)));
        float ry = __fmaf_rn(z,  0.5f,    __fmaf_rn(y, 0.7071f, __fmul_rn(x, -0.5f)));
        float rz = __fmaf_rn(z,  0.7071f, __fmul_rn(x, 0.7071f));   // ROT[1][2]==0
        float k = __fsqrt_rn(sumsq_rn(rx, ry, rz));                 // rho key (post-sqrt!)
        phiA[j] = __fadd_rn(__fdiv_rn(atan2f(ry, rx), TWO_PI_F), 0.5f);
        // stable insertion into (skey, perm), strict > keeps equal keys in order
        int i = j;
        while (i > 0 && skey[i - 1] > k) { skey[i] = skey[i - 1]; perm[i] = perm[i - 1]; i--; }
        skey[i] = k; perm[i] = j;
    }

    // stable phi-sort within parts [0,9) [9,27) [27,54)
    const int segA[3] = {0, 9, 27};
    const int segB[3] = {9, 27, 54};
    for (int sgi = 0; sgi < 3; sgi++) {
        int a = segA[sgi], b = segB[sgi];
        for (int j = a + 1; j < b; j++) {
            int pj = perm[j];
            float f = phiA[pj];
            int i = j;
            while (i > a && phiA[perm[i - 1]] > f) { perm[i] = perm[i - 1]; i--; }
            perm[i] = pj;
        }
    }

    // triangle pass 1: normals / centroids / pos / bad mask
    float tn0[54], tn1[54], tn2[54], tc0[54], tc1[54], tc2[54], tps[54];
    unsigned long long badm = 0ULL;
    float pm = 1.0f;
    int first = -1;
    for (int t = 0; t < 54; t++) {
        int base, len;
        if (t < 9) { base = 0; len = 9; }
        else if (t < 27) { base = 9; len = 18; }
        else { base = 27; len = 27; }
        int loc = t - base + 1;
        int nt = base + (loc == len ? 0 : loc);
        int a = perm[t], b = perm[nt];
        float e1x = gx[a], e1y = gy[a], e1z = gz[a];
        float e2x = gx[b], e2y = gy[b], e2z = gz[b];
        // cross product: mul, mul, sub — no fma contraction (matches XLA)
        float nx = __fsub_rn(__fmul_rn(e1y, e2z), __fmul_rn(e1z, e2y));
        float ny = __fsub_rn(__fmul_rn(e1z, e2x), __fmul_rn(e1x, e2z));
        float nz = __fsub_rn(__fmul_rn(e1x, e2y), __fmul_rn(e1y, e2x));
        float nl = __fsqrt_rn(sumsq_rn(nx, ny, nz));
        bool bad = (nl == 0.0f);
        float ux, uy, uz;
        if (bad) { ux = 0.0f; uy = 0.0f; uz = 0.0f; }
        else {
            ux = __fdiv_rn(nx, nl); uy = __fdiv_rn(ny, nl); uz = __fdiv_rn(nz, nl);
        }
        if (t == 0) pm = (ux > 0.0f) ? 1.0f : -1.0f;
        ux = __fmul_rn(ux, pm); uy = __fmul_rn(uy, pm); uz = __fmul_rn(uz, pm);
        float ccx = __fdiv_rn(__fadd_rn(e1x, e2x), 3.0f);
        float ccy = __fdiv_rn(__fadd_rn(e1y, e2y), 3.0f);
        float ccz = __fdiv_rn(__fadd_rn(e1z, e2z), 3.0f);
        float pos = __fdiv_rn(
            __fadd_rn(__fadd_rn(__fmul_rn(ux, ccx), __fmul_rn(uy, ccy)), __fmul_rn(uz, ccz)),
            SQRT3_F);
        tn0[t] = ux; tn1[t] = uy; tn2[t] = uz;
        tc0[t] = ccx; tc1[t] = ccy; tc2[t] = ccz;
        tps[t] = pos;
        if (bad) badm |= (1ULL << t);
        else if (first < 0) first = t;
    }
    if (first < 0) first = 0;

    // pass 2: polar (from UNreplaced cen) + replaced n/pos/cen, layer-1 MLP
    float s0[10], s1[10];
#pragma unroll
    for (int c = 0; c < 10; c++) { s0[c] = 0.0f; s1[c] = 0.0f; }

    for (int t = 0; t < 54; t++) {
        int src = ((badm >> t) & 1ULL) ? first : t;
        float ccx = tc0[t], ccy = tc1[t], ccz = tc2[t];
        float rho = __fsqrt_rn(sumsq_rn(ccx, ccy, ccz));
        float phi = __fadd_rn(__fdiv_rn(atan2f(ccy, ccx), TWO_PI_F), 0.5f);
        float theta;
        if (rho == 0.0f) theta = 0.0f;
        else {
            float r = __fdiv_rn(ccz, rho);
            r = fminf(1.0f, fmaxf(-1.0f, r));
            theta = __fdiv_rn(acosf(r), PI_F);
        }
        float f[10];
        f[0] = rho; f[1] = theta; f[2] = phi;
        f[3] = tn0[src]; f[4] = tn1[src]; f[5] = tn2[src];
        f[6] = tps[src];
        f[7] = tc0[src]; f[8] = tc1[src]; f[9] = tc2[src];

        int hb = (p * 54 + t) * 10;
#pragma unroll
        for (int c = 0; c < 10; c++) {
            float acc = 0.0f;
#pragma unroll
            for (int k = 0; k < 10; k++) acc += f[k] * sW1[c * 10 + k];
            float h = acc + sb1[c];
            d_h[hb + c] = h;
            s0[c] += h;
            s1[c] += h * h;
        }
    }

    // deterministic per-block reduction of 20 values
    for (int v = 0; v < 20; v++) {
        red[tid] = (v < 10) ? s0[v] : s1[v - 10];
        __syncthreads();
        for (int off = 128; off > 0; off >>= 1) {
            if (tid < off) red[tid] += red[tid + off];
            __syncthreads();
        }
        if (tid == 0) d_part[blockIdx.x * 20 + v] = red[0];
        __syncthreads();
    }
}

// ---------------- BN finalize ----------------
__global__ void bnK(const float* __restrict__ gamma, const float* __restrict__ beta) {
    int c = threadIdx.x;
    __shared__ double S[20];
    if (c < 20) {
        double a = 0.0;
        for (int b = 0; b < NBLK; b++) a += (double)d_part[b * 20 + c];
        S[c] = a;
    }
    __syncthreads();
    if (c < 10) {
        const double M = (double)N_PTS * 54.0;
        double mu = S[c] / M;
        double var = S[c + 10] / M - mu * mu;
        if (var < 0.0) var = 0.0;
        float a = gamma[c] * rsqrtf((float)var + 1e-5f);
        d_bn[c] = a;
        d_bn[10 + c] = beta[c] - (float)mu * a;
    }
}

// ---------------- BN affine + relu + layer2 + sum over 54 ----------------
__global__ __launch_bounds__(256) void outK(const float* __restrict__ W2,
                                            const float* __restrict__ b2,
                                            float* __restrict__ out) {
    __shared__ float sa[10], sb[10], sW2[100], sb2[10];
    int tid = threadIdx.x;
    if (tid < 10) { sa[tid] = d_bn[tid]; sb[tid] = d_bn[10 + tid]; sb2[tid] = b2[tid]; }
    if (tid < 100) sW2[tid] = W2[tid];
    __syncthreads();

    int p = blockIdx.x * blockDim.x + tid;
    float acc[10];
#pragma unroll
    for (int c = 0; c < 10; c++) acc[c] = 0.0f;
    int base = p * 540;
    for (int t = 0; t < 54; t++) {
#pragma unroll
        for (int c = 0; c < 10; c++) {
            float v = d_h[base + t * 10 + c] * sa[c] + sb[c];
            v = fmaxf(v, 0.0f);
            acc[c] += v;
        }
    }
#pragma unroll
    for (int c = 0; c < 10; c++) {
        float o = 54.0f * sb2[c];
#pragma unroll
        for (int j = 0; j < 10; j++) o += acc[j] * sW2[c * 10 + j];
        out[p * 10 + c] = o;
    }
}

// ---------------- launch ----------------
extern "C" void kernel_launch(void* const* d_in, const int* in_sizes, int n_in,
                              void* d_out, int out_size) {
    const float* center = (const float*)d_in[0];
    // d_in[1] = offset (unused, single batch)
    const float* W1 = (const float*)d_in[2];
    const float* b1 = (const float*)d_in[3];
    const float* gamma = (const float*)d_in[4];
    const float* beta = (const float*)d_in[5];
    const float* W2 = (const float*)d_in[6];
    const float* b2 = (const float*)d_in[7];
    float* out = (float*)d_out;

    zeroK<<<16, 256>>>();
    countK<<<256, 256>>>(center);
    scanK<<<1, 1024>>>();
    scatterK<<<256, 256>>>(center);
    knnK<<<256, 256>>>();
    featK<<<256, 256>>>(center, W1, b1);
    bnK<<<1, 32>>>(gamma, beta);
    outK<<<256, 256>>>(W2, b2, out);
}

// round 4
// speedup vs baseline: 2.5497x; 2.5497x over previous
#include <cuda_runtime.h>
#include <math_constants.h>

#define N_PTS 65536
#define KNNK 54
#define GRIDD 16
#define NCELL 4096
#define CELLH 0.0625f
#define FBLK 1024    // featK: 1024 blocks x 64 threads

#define TWO_PI_F 6.28318530717958647692f
#define PI_F     3.14159265358979323846f
#define SQRT3_F  1.73205080756887729353f

// ---------------- scratch (static device memory; no allocation) ----------------
__device__ float4 d_sorted[N_PTS];
__device__ int d_cellStart[NCELL + 1];
__device__ int d_cellPtr[NCELL];
__device__ int d_cnt[NCELL];
__device__ unsigned long long d_key[N_PTS * KNNK];  // (mapped-d<<32)|idx, unsorted slots
__device__ float d_h[N_PTS * KNNK * 10];            // transposed: [ch][p]
__device__ float d_part[FBLK * 20];
__device__ float d_bn[20];

__device__ __forceinline__ int cellCoord(float v) {
    int c = (int)floorf(v * 16.0f);
    c = c < 0 ? 0 : c;
    return c > (GRIDD - 1) ? (GRIDD - 1) : c;
}

// XLA-style sum of squares: ((x*x + y*y) + z*z), separate mul/add, round-to-nearest
__device__ __forceinline__ float sumsq_rn(float x, float y, float z) {
    return __fadd_rn(__fadd_rn(__fmul_rn(x, x), __fmul_rn(y, y)), __fmul_rn(z, z));
}

// cuBLAS-style K=3 dot: ascending-k fma chain
__device__ __forceinline__ float dot3_fma(float ax, float ay, float az,
                                          float bx, float by, float bz) {
    return __fmaf_rn(az, bz, __fmaf_rn(ay, by, __fmul_rn(ax, bx)));
}

// order-preserving float->uint map (no NaNs in use; no -0 producible here)
__device__ __forceinline__ unsigned mapf(float d) {
    unsigned u = __float_as_uint(d);
    return (u & 0x80000000u) ? ~u : (u | 0x80000000u);
}
__device__ __forceinline__ float unmapf(unsigned m) {
    unsigned u = (m & 0x80000000u) ? (m & 0x7FFFFFFFu) : ~m;
    return __uint_as_float(u);
}

// ---------------- grid build ----------------
__global__ void zeroK() {
    int i = blockIdx.x * blockDim.x + threadIdx.x;
    if (i < NCELL) d_cnt[i] = 0;
}

__global__ void countK(const float* __restrict__ c) {
    int i = blockIdx.x * blockDim.x + threadIdx.x;
    if (i >= N_PTS) return;
    int cx = cellCoord(c[3 * i]);
    int cy = cellCoord(c[3 * i + 1]);
    int cz = cellCoord(c[3 * i + 2]);
    atomicAdd(&d_cnt[(cz * GRIDD + cy) * GRIDD + cx], 1);
}

__global__ __launch_bounds__(1024) void scanK() {
    __shared__ int s[1024];
    int t = threadIdx.x;
    int v0 = d_cnt[4 * t], v1 = d_cnt[4 * t + 1], v2 = d_cnt[4 * t + 2], v3 = d_cnt[4 * t + 3];
    int tot = v0 + v1 + v2 + v3;
    s[t] = tot;
    __syncthreads();
    for (int off = 1; off < 1024; off <<= 1) {
        int x = (t >= off) ? s[t - off] : 0;
        __syncthreads();
        s[t] += x;
        __syncthreads();
    }
    int excl = s[t] - tot;
    d_cellStart[4 * t] = excl;
    d_cellStart[4 * t + 1] = excl + v0;
    d_cellStart[4 * t + 2] = excl + v0 + v1;
    d_cellStart[4 * t + 3] = excl + v0 + v1 + v2;
    d_cellPtr[4 * t] = excl;
    d_cellPtr[4 * t + 1] = excl + v0;
    d_cellPtr[4 * t + 2] = excl + v0 + v1;
    d_cellPtr[4 * t + 3] = excl + v0 + v1 + v2;
    if (t == 1023) d_cellStart[NCELL] = s[1023];
}

__global__ void scatterK(const float* __restrict__ c) {
    int i = blockIdx.x * blockDim.x + threadIdx.x;
    if (i >= N_PTS) return;
    float x = c[3 * i], y = c[3 * i + 1], z = c[3 * i + 2];
    int cid = (cellCoord(z) * GRIDD + cellCoord(y)) * GRIDD + cellCoord(x);
    int pos = atomicAdd(&d_cellPtr[cid], 1);
    d_sorted[pos] = make_float4(x, y, z, __int_as_float(i));
}

// ---------------- KNN: unsorted top-54 in shared memory ----------------
__global__ __launch_bounds__(64) void knnK() {
    __shared__ unsigned long long sK[KNNK * 64];
    int tid = threadIdx.x;
    int t = blockIdx.x * 64 + tid;
    float4 q = d_sorted[t];
    int qi = __float_as_int(q.w);
    float qx = q.x, qy = q.y, qz = q.z;
    float qsq = sumsq_rn(qx, qy, qz);
    int cx = cellCoord(qx), cy = cellCoord(qy), cz = cellCoord(qz);

    const unsigned long long INIT =
        ((unsigned long long)0xFF800000u << 32) | 0x7FFFFFFFu;  // (+inf, INT_MAX)
#pragma unroll
    for (int j = 0; j < KNNK; j++) sK[j * 64 + tid] = INIT;
    float worst_d = CUDART_INF_F;
    int worst_i = 0x7FFFFFFF;
    int worst_s = 0;

    int maxm = cx; if (GRIDD - 1 - cx > maxm) maxm = GRIDD - 1 - cx;
    if (cy > maxm) maxm = cy; if (GRIDD - 1 - cy > maxm) maxm = GRIDD - 1 - cy;
    if (cz > maxm) maxm = cz; if (GRIDD - 1 - cz > maxm) maxm = GRIDD - 1 - cz;

    for (int m = 0;; m++) {
        int zlo = cz - m < 0 ? 0 : cz - m;
        int zhi = cz + m > GRIDD - 1 ? GRIDD - 1 : cz + m;
        for (int z = zlo; z <= zhi; z++) {
            int adz = z - cz; adz = adz < 0 ? -adz : adz;
            int ylo = cy - m < 0 ? 0 : cy - m;
            int yhi = cy + m > GRIDD - 1 ? GRIDD - 1 : cy + m;
            for (int y = ylo; y <= yhi; y++) {
                int ady = y - cy; ady = ady < 0 ? -ady : ady;
                int xlo = cx - m < 0 ? 0 : cx - m;
                int xhi = cx + m > GRIDD - 1 ? GRIDD - 1 : cx + m;
                for (int x = xlo; x <= xhi; x++) {
                    int adx = x - cx; adx = adx < 0 ? -adx : adx;
                    int cheb = adx > ady ? adx : ady;
                    if (adz > cheb) cheb = adz;
                    if (cheb != m) continue;
                    int cid = (z * GRIDD + y) * GRIDD + x;
                    int s = d_cellStart[cid], e = d_cellStart[cid + 1];
                    for (int p = s; p < e; p++) {
                        float4 pt = d_sorted[p];
                        float psq = sumsq_rn(pt.x, pt.y, pt.z);
                        float dot = dot3_fma(qx, qy, qz, pt.x, pt.y, pt.z);
                        float d = __fsub_rn(__fadd_rn(qsq, psq), __fmul_rn(2.0f, dot));
                        int pi = __float_as_int(pt.w);
                        if (d < worst_d || (d == worst_d && pi < worst_i)) {
                            sK[worst_s * 64 + tid] =
                                ((unsigned long long)mapf(d) << 32) | (unsigned)pi;
                            // branch-free rescan for new worst
                            unsigned long long best = 0ULL;
                            int bs = 0;
#pragma unroll
                            for (int j = 0; j < KNNK; j++) {
                                unsigned long long v = sK[j * 64 + tid];
                                if (v > best) { best = v; bs = j; }
                            }
                            worst_s = bs;
                            worst_d = unmapf((unsigned)(best >> 32));
                            worst_i = (int)(best & 0xFFFFFFFFu);
                        }
                    }
                }
            }
        }
        float rr = (float)m * CELLH;
        if (worst_d + 4e-6f < rr * rr) break;
        if (m >= maxm) break;
    }
#pragma unroll
    for (int j = 0; j < KNNK; j++) d_key[qi * KNNK + j] = sK[j * 64 + tid];
}

// ---------------- features + layer1 + BN partial sums ----------------
__global__ __launch_bounds__(64) void featK(const float* __restrict__ cen,
                                            const float* __restrict__ W1,
                                            const float* __restrict__ b1) {
    __shared__ float sW1[100], sb1[10];
    __shared__ float sRho[54 * 64];
    __shared__ float sPhi[54 * 64];
    __shared__ int sPermA[54 * 64];
    __shared__ float sRed[64];
    int* sPermB = (int*)sRho;   // rho dead after rho-rank
    int* sIdx = (int*)sPhi;     // phi dead after phi-rank

    int tid = threadIdx.x;
    for (int i = tid; i < 100; i += 64) sW1[i] = W1[i];
    if (tid < 10) sb1[tid] = b1[tid];
    __syncthreads();

    int p = blockIdx.x * 64 + tid;
    float qx = cen[3 * p], qy = cen[3 * p + 1], qz = cen[3 * p + 2];
    const unsigned long long* myKey = d_key + (size_t)p * KNNK;

    // phase A: per-slot rho & phi keys (order-independent per neighbor)
    for (int j = 0; j < 54; j++) {
        int nb = (int)(myKey[j] & 0xFFFFFFFFull);
        float x = __fsub_rn(cen[3 * nb], qx);
        float y = __fsub_rn(cen[3 * nb + 1], qy);
        float z = __fsub_rn(cen[3 * nb + 2], qz);
        float rx = __fmaf_rn(z, -0.5f,    __fmaf_rn(y, 0.7071f, __fmul_rn(x,  0.5f)));
        float ry = __fmaf_rn(z,  0.5f,    __fmaf_rn(y, 0.7071f, __fmul_rn(x, -0.5f)));
        float rz = __fmaf_rn(z,  0.7071f, __fmul_rn(x, 0.7071f));
        sRho[j * 64 + tid] = __fsqrt_rn(sumsq_rn(rx, ry, rz));
        sPhi[j * 64 + tid] = __fadd_rn(__fdiv_rn(atan2f(ry, rx), TWO_PI_F), 0.5f);
    }

    // rho rank-sort; comparator lex(rho, key64) == stable rho-sort of (d,idx)-asc order
    for (int j = 0; j < 54; j++) {
        float kj = sRho[j * 64 + tid];
        int r = 0;
        for (int i = 0; i < 54; i++) {
            float ki = sRho[i * 64 + tid];
            if (ki < kj) r++;
            else if (ki == kj && i != j) {
                if (myKey[i] < myKey[j]) r++;   // rare tie path
            }
        }
        sPermA[r * 64 + tid] = j;
    }

    // stable phi rank-sort within segments [0,9) [9,27) [27,54)
    {
        const int segA[3] = {0, 9, 27};
        const int segB[3] = {9, 27, 54};
        for (int sgi = 0; sgi < 3; sgi++) {
            int a = segA[sgi], b = segB[sgi];
            for (int pos = a; pos < b; pos++) {
                int sl = sPermA[pos * 64 + tid];
                float kp = sPhi[sl * 64 + tid];
                int r = 0;
                for (int i = a; i < b; i++) {
                    int si = sPermA[i * 64 + tid];
                    float ki = sPhi[si * 64 + tid];
                    r += (ki < kp || (ki == kp && i < pos)) ? 1 : 0;
                }
                sPermB[(a + r) * 64 + tid] = sl;
            }
        }
    }

    // materialize sorted neighbor indices (destroys phi)
    for (int t = 0; t < 54; t++) {
        int sl = sPermB[t * 64 + tid];
        sIdx[t * 64 + tid] = (int)(myKey[sl] & 0xFFFFFFFFull);
    }

    // pre-pass: bad mask, pm (sign from triangle 0), first good triangle
    unsigned long long badm = 0ULL;
    float pm = 1.0f;
    int first = -1;
    for (int t = 0; t < 54; t++) {
        int base, len;
        if (t < 9) { base = 0; len = 9; }
        else if (t < 27) { base = 9; len = 18; }
        else { base = 27; len = 27; }
        int loc = t - base + 1;
        int nt = base + (loc == len ? 0 : loc);
        int na = sIdx[t * 64 + tid], nb = sIdx[nt * 64 + tid];
        float e1x = __fsub_rn(cen[3 * na], qx);
        float e1y = __fsub_rn(cen[3 * na + 1], qy);
        float e1z = __fsub_rn(cen[3 * na + 2], qz);
        float e2x = __fsub_rn(cen[3 * nb], qx);
        float e2y = __fsub_rn(cen[3 * nb + 1], qy);
        float e2z = __fsub_rn(cen[3 * nb + 2], qz);
        float nx = __fsub_rn(__fmul_rn(e1y, e2z), __fmul_rn(e1z, e2y));
        float ny = __fsub_rn(__fmul_rn(e1z, e2x), __fmul_rn(e1x, e2z));
        float nz = __fsub_rn(__fmul_rn(e1x, e2y), __fmul_rn(e1y, e2x));
        float nl = __fsqrt_rn(sumsq_rn(nx, ny, nz));
        bool bad = (nl == 0.0f);
        if (t == 0) {
            float ux = bad ? 0.0f : __fdiv_rn(nx, nl);
            pm = (ux > 0.0f) ? 1.0f : -1.0f;
        }
        if (bad) badm |= (1ULL << t);
        else if (first < 0) first = t;
    }
    if (first < 0) first = 0;

    // triangle evaluator (bit-identical to round-3 expressions)
    auto evalTri = [&](int t, float& ux, float& uy, float& uz,
                       float& ccx, float& ccy, float& ccz, float& pos) {
        int base, len;
        if (t < 9) { base = 0; len = 9; }
        else if (t < 27) { base = 9; len = 18; }
        else { base = 27; len = 27; }
        int loc = t - base + 1;
        int nt = base + (loc == len ? 0 : loc);
        int na = sIdx[t * 64 + tid], nb = sIdx[nt * 64 + tid];
        float e1x = __fsub_rn(cen[3 * na], qx);
        float e1y = __fsub_rn(cen[3 * na + 1], qy);
        float e1z = __fsub_rn(cen[3 * na + 2], qz);
        float e2x = __fsub_rn(cen[3 * nb], qx);
        float e2y = __fsub_rn(cen[3 * nb + 1], qy);
        float e2z = __fsub_rn(cen[3 * nb + 2], qz);
        float nx = __fsub_rn(__fmul_rn(e1y, e2z), __fmul_rn(e1z, e2y));
        float ny = __fsub_rn(__fmul_rn(e1z, e2x), __fmul_rn(e1x, e2z));
        float nz = __fsub_rn(__fmul_rn(e1x, e2y), __fmul_rn(e1y, e2x));
        float nl = __fsqrt_rn(sumsq_rn(nx, ny, nz));
        bool bad = (nl == 0.0f);
        if (bad) { ux = 0.0f; uy = 0.0f; uz = 0.0f; }
        else {
            ux = __fdiv_rn(nx, nl); uy = __fdiv_rn(ny, nl); uz = __fdiv_rn(nz, nl);
        }
        ux = __fmul_rn(ux, pm); uy = __fmul_rn(uy, pm); uz = __fmul_rn(uz, pm);
        ccx = __fdiv_rn(__fadd_rn(e1x, e2x), 3.0f);
        ccy = __fdiv_rn(__fadd_rn(e1y, e2y), 3.0f);
        ccz = __fdiv_rn(__fadd_rn(e1z, e2z), 3.0f);
        pos = __fdiv_rn(
            __fadd_rn(__fadd_rn(__fmul_rn(ux, ccx), __fmul_rn(uy, ccy)), __fmul_rn(uz, ccz)),
            SQRT3_F);
    };

    // replacement values from the first good triangle
    float fux, fuy, fuz, fcx, fcy, fcz, fpos;
    evalTri(first, fux, fuy, fuz, fcx, fcy, fcz, fpos);

    float s0[10], s1[10];
#pragma unroll
    for (int c = 0; c < 10; c++) { s0[c] = 0.0f; s1[c] = 0.0f; }

    for (int t = 0; t < 54; t++) {
        float ux, uy, uz, ccx, ccy, ccz, pos;
        evalTri(t, ux, uy, uz, ccx, ccy, ccz, pos);
        bool bad = ((badm >> t) & 1ULL) != 0ULL;

        // polar from OWN (unreplaced) centroid
        float rho = __fsqrt_rn(sumsq_rn(ccx, ccy, ccz));
        float phi = __fadd_rn(__fdiv_rn(atan2f(ccy, ccx), TWO_PI_F), 0.5f);
        float theta;
        if (rho == 0.0f) theta = 0.0f;
        else {
            float r = __fdiv_rn(ccz, rho);
            r = fminf(1.0f, fmaxf(-1.0f, r));
            theta = __fdiv_rn(acosf(r), PI_F);
        }
        float f[10];
        f[0] = rho; f[1] = theta; f[2] = phi;
        f[3] = bad ? fux : ux; f[4] = bad ? fuy : uy; f[5] = bad ? fuz : uz;
        f[6] = bad ? fpos : pos;
        f[7] = bad ? fcx : ccx; f[8] = bad ? fcy : ccy; f[9] = bad ? fcz : ccz;

        int chBase = t * 10;
#pragma unroll
        for (int c = 0; c < 10; c++) {
            float acc = 0.0f;
#pragma unroll
            for (int k = 0; k < 10; k++) acc += f[k] * sW1[c * 10 + k];
            float h = acc + sb1[c];
            d_h[(size_t)(chBase + c) * N_PTS + p] = h;   // coalesced (lane-contiguous)
            s0[c] += h;
            s1[c] += h * h;
        }
    }

    // deterministic per-block reduction of 20 values
    for (int v = 0; v < 20; v++) {
        sRed[tid] = (v < 10) ? s0[v] : s1[v - 10];
        __syncthreads();
        for (int off = 32; off > 0; off >>= 1) {
            if (tid < off) sRed[tid] += sRed[tid + off];
            __syncthreads();
        }
        if (tid == 0) d_part[blockIdx.x * 20 + v] = sRed[0];
        __syncthreads();
    }
}

// ---------------- BN finalize: warp-per-channel reduction over FBLK partials ----------------
__global__ __launch_bounds__(640) void bnK(const float* __restrict__ gamma,
                                           const float* __restrict__ beta) {
    __shared__ float S[20];
    int tid = threadIdx.x;
    int w = tid / 32, l = tid % 32;
    float a = 0.0f;
    for (int k = l; k < FBLK; k += 32) a += d_part[k * 20 + w];
#pragma unroll
    for (int off = 16; off > 0; off >>= 1) a += __shfl_down_sync(0xFFFFFFFFu, a, off);
    if (l == 0) S[w] = a;
    __syncthreads();
    if (tid < 10) {
        const double M = (double)N_PTS * 54.0;
        double mu = (double)S[tid] / M;
        double var = (double)S[tid + 10] / M - mu * mu;
        if (var < 0.0) var = 0.0;
        float sc = gamma[tid] * rsqrtf((float)var + 1e-5f);
        d_bn[tid] = sc;
        d_bn[10 + tid] = beta[tid] - (float)mu * sc;
    }
}

// ---------------- BN affine + relu + layer2 + sum over 54 ----------------
__global__ __launch_bounds__(256) void outK(const float* __restrict__ W2,
                                            const float* __restrict__ b2,
                                            float* __restrict__ out) {
    __shared__ float sa[10], sb[10], sW2[100], sb2[10];
    int tid = threadIdx.x;
    if (tid < 10) { sa[tid] = d_bn[tid]; sb[tid] = d_bn[10 + tid]; sb2[tid] = b2[tid]; }
    if (tid < 100) sW2[tid] = W2[tid];
    __syncthreads();

    int p = blockIdx.x * blockDim.x + tid;
    float acc[10];
#pragma unroll
    for (int c = 0; c < 10; c++) acc[c] = 0.0f;
    for (int t = 0; t < 54; t++) {
#pragma unroll
        for (int c = 0; c < 10; c++) {
            float v = d_h[(size_t)(t * 10 + c) * N_PTS + p] * sa[c] + sb[c];
            v = fmaxf(v, 0.0f);
            acc[c] += v;
        }
    }
#pragma unroll
    for (int c = 0; c < 10; c++) {
        float o = 54.0f * sb2[c];
#pragma unroll
        for (int j = 0; j < 10; j++) o += acc[j] * sW2[c * 10 + j];
        out[p * 10 + c] = o;
    }
}

// ---------------- launch ----------------
extern "C" void kernel_launch(void* const* d_in, const int* in_sizes, int n_in,
                              void* d_out, int out_size) {
    const float* center = (const float*)d_in[0];
    const float* W1 = (const float*)d_in[2];
    const float* b1 = (const float*)d_in[3];
    const float* gamma = (const float*)d_in[4];
    const float* beta = (const float*)d_in[5];
    const float* W2 = (const float*)d_in[6];
    const float* b2 = (const float*)d_in[7];
    float* out = (float*)d_out;

    zeroK<<<16, 256>>>();
    countK<<<256, 256>>>(center);
    scanK<<<1, 1024>>>();
    scatterK<<<256, 256>>>(center);
    knnK<<<1024, 64>>>();
    featK<<<FBLK, 64>>>(center, W1, b1);
    bnK<<<1, 640>>>(gamma, beta);
    outK<<<256, 256>>>(W2, b2, out);
}